// round 3
// baseline (speedup 1.0000x reference)
#include <cuda_runtime.h>

#define Bn   4
#define CIN  64
#define Hc   128
#define Wc   128
#define COUT 64
#define Kk   3
#define DGn  8
#define KKn  9
#define HOn  128
#define WOn  128
#define CGn  8

// Scratch (device globals; no runtime allocation allowed)
// x re-laid out per deformable group: [b][dg][y][x][cg]  (pixel stride = 32B)
__device__ float g_xt[Bn * DGn * Hc * Wc * CGn];
// weights re-laid out AND duplicated for f32x2: [kk][c][2*COUT], w at 2o and 2o+1
__device__ float g_wt2[KKn * CIN * 2 * COUT];

// packed f32x2 fused multiply-add: d = a * b + d  (2 FMAs / issue slot)
#define FFMA2(d, a, b) \
    asm volatile("fma.rn.f32x2 %0, %1, %2, %0;" : "+l"(d) : "l"(a), "l"(b))

static __device__ __forceinline__ float2 u2f(unsigned long long v) {
    float2 f;
    f.x = __uint_as_float((unsigned)(v & 0xffffffffull));
    f.y = __uint_as_float((unsigned)(v >> 32));
    return f;
}

// ---------------------------------------------------------------------------
// x: [B, C=dg*8+cg, H*W]  ->  g_xt: [b][dg][p][cg]
// ---------------------------------------------------------------------------
__global__ void transpose_x_kernel(const float* __restrict__ x) {
    __shared__ float s[8][260];
    const int b   = blockIdx.z;
    const int dg  = blockIdx.y;
    const int p0  = blockIdx.x * 256;
    const int tid = threadIdx.x;

    #pragma unroll
    for (int ch = 0; ch < 8; ++ch)
        s[ch][tid] = x[(size_t)(b * CIN + dg * CGn + ch) * (Hc * Wc) + p0 + tid];
    __syncthreads();

    float* dst = g_xt + ((size_t)(b * DGn + dg) * (Hc * Wc) + p0) * CGn;
    #pragma unroll
    for (int i = 0; i < 8; ++i) {
        const int idx = i * 256 + tid;
        dst[idx] = s[idx & 7][idx >> 3];
    }
}

// ---------------------------------------------------------------------------
// weight: [COUT, CIN, K, K] -> g_wt2[kk][c][2o] = g_wt2[kk][c][2o+1] = w
// ---------------------------------------------------------------------------
__global__ void transpose_w_kernel(const float* __restrict__ w) {
    int idx = blockIdx.x * 256 + threadIdx.x;
    if (idx >= KKn * CIN * COUT) return;
    int kk  = idx / (CIN * COUT);
    int rem = idx - kk * (CIN * COUT);
    int c   = rem / COUT;
    int o   = rem - c * COUT;
    const float v = w[(size_t)(o * CIN + c) * KKn + kk];
    float* dst = g_wt2 + ((size_t)kk * CIN + c) * (2 * COUT) + 2 * o;
    dst[0] = v;
    dst[1] = v;
}

// ---------------------------------------------------------------------------
// Fused deformable-conv. Block = one output row (b, y).
// Per tap kk: bilinear-sample 64ch x 128px into smem, then GEMM step with
// 8o x 4px register tiles using packed f32x2 FFMA (2 MACs/issue).
// ---------------------------------------------------------------------------
__global__ void __launch_bounds__(256, 2) dcn_kernel(
    const float* __restrict__ offset,
    const float* __restrict__ bias,
    float* __restrict__ out)
{
    __shared__ __align__(16) float cols[CIN][WOn];   // 32 KB

    const int bid = blockIdx.x;          // 0 .. B*HO-1
    const int b   = bid >> 7;
    const int y   = bid & 127;
    const int tid = threadIdx.x;
    const int og  = tid >> 5;            // 0..7  -> outputs og*8 .. og*8+7
    const int pg  = tid & 31;            // 0..31 -> pixels  pg*4 .. pg*4+3

    // acc2[o][jp]: packed pair of pixels {pg*4+2jp, pg*4+2jp+1} for output og*8+o
    unsigned long long acc2[8][2];
    #pragma unroll
    for (int i = 0; i < 8; ++i) {
        acc2[i][0] = 0ull;
        acc2[i][1] = 0ull;
    }

    const float* off_b = offset + (size_t)b * (2 * DGn * KKn * HOn * WOn) + (size_t)y * WOn;
    const float* xt_b  = g_xt + (size_t)b * (DGn * Hc * Wc * CGn);

    for (int kk = 0; kk < KKn; ++kk) {
        const int kh = kk / 3;
        const int kw = kk - kh * 3;

        // ---- sampling: 1024 points (8 dg x 128 px), 4 per thread ----
        #pragma unroll
        for (int it = 0; it < 4; ++it) {
            const int t  = tid + it * 256;
            const int dg = t >> 7;
            const int px = t & 127;

            const float* op = off_b + (size_t)((dg * KKn + kk) * 2) * (HOn * WOn) + px;
            const float oy = op[0];
            const float ox = op[HOn * WOn];

            const float py  = (float)(y - 1 + kh) + oy;
            const float pxx = (float)(px - 1 + kw) + ox;
            const float y0f = floorf(py);
            const float x0f = floorf(pxx);
            const float ly  = py - y0f;
            const float lx  = pxx - x0f;
            const int y0 = (int)y0f;
            const int x0 = (int)x0f;
            const float hy = 1.0f - ly, hx = 1.0f - lx;

            float w00 = hy * hx, w01 = hy * lx, w10 = ly * hx, w11 = ly * lx;
            const bool yv0 = (y0 >= 0) && (y0 < Hc);
            const bool yv1 = (y0 + 1 >= 0) && (y0 + 1 < Hc);
            const bool xv0 = (x0 >= 0) && (x0 < Wc);
            const bool xv1 = (x0 + 1 >= 0) && (x0 + 1 < Wc);
            if (!(yv0 && xv0)) w00 = 0.0f;
            if (!(yv0 && xv1)) w01 = 0.0f;
            if (!(yv1 && xv0)) w10 = 0.0f;
            if (!(yv1 && xv1)) w11 = 0.0f;

            const int iy0 = min(max(y0, 0), Hc - 1);
            const int iy1 = min(max(y0 + 1, 0), Hc - 1);
            const int ix0 = min(max(x0, 0), Wc - 1);
            const int ix1 = min(max(x0 + 1, 0), Wc - 1);

            const float* xg = xt_b + (size_t)dg * (Hc * Wc * CGn);
            const float4* p00 = (const float4*)(xg + (size_t)(iy0 * Wc + ix0) * CGn);
            const float4* p01 = (const float4*)(xg + (size_t)(iy0 * Wc + ix1) * CGn);
            const float4* p10 = (const float4*)(xg + (size_t)(iy1 * Wc + ix0) * CGn);
            const float4* p11 = (const float4*)(xg + (size_t)(iy1 * Wc + ix1) * CGn);

            float* dst = &cols[dg * CGn][px];
            #pragma unroll
            for (int g = 0; g < 2; ++g) {
                const float4 v00 = p00[g];
                const float4 v01 = p01[g];
                const float4 v10 = p10[g];
                const float4 v11 = p11[g];
                dst[(g * 4 + 0) * WOn] = w00 * v00.x + w01 * v01.x + w10 * v10.x + w11 * v11.x;
                dst[(g * 4 + 1) * WOn] = w00 * v00.y + w01 * v01.y + w10 * v10.y + w11 * v11.y;
                dst[(g * 4 + 2) * WOn] = w00 * v00.z + w01 * v01.z + w10 * v10.z + w11 * v11.z;
                dst[(g * 4 + 3) * WOn] = w00 * v00.w + w01 * v01.w + w10 * v10.w + w11 * v11.w;
            }
        }
        __syncthreads();

        // ---- GEMM step (f32x2): acc2 += wdup[kk][c][og..] * cols[c][pg*4..] ----
        const float* wk2 = g_wt2 + ((size_t)kk * CIN) * (2 * COUT) + og * 16;
        #pragma unroll 8
        for (int c = 0; c < CIN; ++c) {
            const ulonglong2 cv = *(const ulonglong2*)&cols[c][pg * 4];
            const ulonglong2* wp = (const ulonglong2*)(wk2 + c * (2 * COUT));
            const ulonglong2 wA = wp[0];   // dup(o0), dup(o1)
            const ulonglong2 wB = wp[1];   // dup(o2), dup(o3)
            const ulonglong2 wC = wp[2];   // dup(o4), dup(o5)
            const ulonglong2 wD = wp[3];   // dup(o6), dup(o7)
            FFMA2(acc2[0][0], wA.x, cv.x); FFMA2(acc2[0][1], wA.x, cv.y);
            FFMA2(acc2[1][0], wA.y, cv.x); FFMA2(acc2[1][1], wA.y, cv.y);
            FFMA2(acc2[2][0], wB.x, cv.x); FFMA2(acc2[2][1], wB.x, cv.y);
            FFMA2(acc2[3][0], wB.y, cv.x); FFMA2(acc2[3][1], wB.y, cv.y);
            FFMA2(acc2[4][0], wC.x, cv.x); FFMA2(acc2[4][1], wC.x, cv.y);
            FFMA2(acc2[5][0], wC.y, cv.x); FFMA2(acc2[5][1], wC.y, cv.y);
            FFMA2(acc2[6][0], wD.x, cv.x); FFMA2(acc2[6][1], wD.x, cv.y);
            FFMA2(acc2[7][0], wD.y, cv.x); FFMA2(acc2[7][1], wD.y, cv.y);
        }
        __syncthreads();
    }

    // ---- epilogue: unpack, add bias, vectorized stores ----
    #pragma unroll
    for (int j = 0; j < 8; ++j) {
        const int o = og * 8 + j;
        const float bv = bias[o];
        const float2 p0 = u2f(acc2[j][0]);
        const float2 p1 = u2f(acc2[j][1]);
        float4 r;
        r.x = p0.x + bv;
        r.y = p0.y + bv;
        r.z = p1.x + bv;
        r.w = p1.y + bv;
        *(float4*)&out[((size_t)(b * COUT + o) * HOn + y) * WOn + pg * 4] = r;
    }
}

extern "C" void kernel_launch(void* const* d_in, const int* in_sizes, int n_in,
                              void* d_out, int out_size) {
    const float* x      = (const float*)d_in[0];
    const float* offset = (const float*)d_in[1];
    const float* weight = (const float*)d_in[2];
    const float* bias   = (const float*)d_in[3];
    float* out = (float*)d_out;

    transpose_x_kernel<<<dim3((Hc * Wc) / 256, DGn, Bn), 256>>>(x);
    transpose_w_kernel<<<(KKn * CIN * COUT + 255) / 256, 256>>>(weight);
    dcn_kernel<<<Bn * HOn, 256>>>(offset, bias, out);
}

// round 5
// speedup vs baseline: 2.1411x; 2.1411x over previous
#include <cuda_runtime.h>
#include <cuda_bf16.h>
#include <cstdint>

#define Bn   4
#define CIN  64
#define Hc   128
#define Wc   128
#define COUT 64
#define DGn  8
#define KKn  9
#define HOn  128
#define WOn  128
#define CGn  8
#define HWp  (HOn * WOn)

// ---------------- scratch (device globals; no runtime alloc) ----------------
__device__ float g_xt[Bn * DGn * Hc * Wc * CGn];     // x: [b][dg][y][x][cg] fp32
__device__ __nv_bfloat16 g_whi[KKn * COUT * CIN];    // weight hi: per-tap [o][c] bf16, PRE-SWIZZLED SW128
__device__ __nv_bfloat16 g_wlo[KKn * COUT * CIN];    // weight lo: same layout

#define SWZ(off) ((off) ^ (((off) >> 3) & 0x70))

// ---------------- smem layout (dynamic, 49152 B) ----------------
#define SM_A_HI  0
#define SM_A_LO  16384
#define SM_W_HI  32768
#define SM_W_LO  40960
#define SM_TOTAL 49152

static __device__ __forceinline__ uint32_t smem_u32(const void* p) {
    uint32_t a;
    asm("{ .reg .u64 t; cvta.to.shared.u64 t, %1; cvt.u32.u64 %0, t; }" : "=r"(a) : "l"(p));
    return a;
}
static __device__ __forceinline__ void ldsm_x4(uint32_t* r, uint32_t addr) {
    asm volatile("ldmatrix.sync.aligned.m8n8.x4.shared.b16 {%0,%1,%2,%3}, [%4];"
                 : "=r"(r[0]), "=r"(r[1]), "=r"(r[2]), "=r"(r[3]) : "r"(addr));
}
static __device__ __forceinline__ void mma_bf16(float* d, const uint32_t* a, const uint32_t* b) {
    asm volatile("mma.sync.aligned.m16n8k16.row.col.f32.bf16.bf16.f32 "
                 "{%0,%1,%2,%3}, {%4,%5,%6,%7}, {%8,%9}, {%0,%1,%2,%3};"
                 : "+f"(d[0]), "+f"(d[1]), "+f"(d[2]), "+f"(d[3])
                 : "r"(a[0]), "r"(a[1]), "r"(a[2]), "r"(a[3]), "r"(b[0]), "r"(b[1]));
}

// ---------------------------------------------------------------------------
// x: [B, C=dg*8+cg, H*W] -> g_xt: [b][dg][p][cg]  (fp32, dg-blocked)
// ---------------------------------------------------------------------------
__global__ void transpose_x_kernel(const float* __restrict__ x) {
    __shared__ float s[8][260];
    const int b = blockIdx.z, dg = blockIdx.y, p0 = blockIdx.x * 256, tid = threadIdx.x;
    #pragma unroll
    for (int ch = 0; ch < 8; ++ch)
        s[ch][tid] = x[(size_t)(b * CIN + dg * CGn + ch) * (Hc * Wc) + p0 + tid];
    __syncthreads();
    float* dst = g_xt + ((size_t)(b * DGn + dg) * (Hc * Wc) + p0) * CGn;
    #pragma unroll
    for (int i = 0; i < 8; ++i) {
        const int idx = i * 256 + tid;
        dst[idx] = s[idx & 7][idx >> 3];
    }
}

// ---------------------------------------------------------------------------
// weight [COUT][CIN][3][3] -> per-tap 64x64 bf16 hi/lo tiles [o][c], SW128-swizzled
// ---------------------------------------------------------------------------
__global__ void prep_w_kernel(const float* __restrict__ w) {
    int idx = blockIdx.x * 256 + threadIdx.x;
    if (idx >= KKn * COUT * CIN) return;
    int kk  = idx / (COUT * CIN);
    int rem = idx - kk * (COUT * CIN);
    int o   = rem / CIN;
    int c   = rem - o * CIN;
    const float v = w[(size_t)(o * CIN + c) * KKn + kk];
    __nv_bfloat16 hi = __float2bfloat16_rn(v);
    __nv_bfloat16 lo = __float2bfloat16_rn(v - __bfloat162float(hi));
    uint32_t off = SWZ((uint32_t)(o * 128 + c * 2));
    g_whi[(size_t)kk * 4096 + off / 2] = hi;
    g_wlo[(size_t)kk * 4096 + off / 2] = lo;
}

// ---------------------------------------------------------------------------
// Fused deformable conv. Block = one output row (b,y); 8 warps.
// Per tap: stage W hi/lo (16KB), bilinear-sample 128px x 64c into bf16 hi/lo
// A-tiles (SW128), then HMMA: warp w owns px-tile [w*16, w*16+16) x all 64 out.
// 3 split combos (AhBh + AhBl + AlBh) accumulate fp32 in registers over 9 taps.
// ---------------------------------------------------------------------------
__global__ void __launch_bounds__(256, 2) dcn_kernel(
    const float* __restrict__ offset,
    const float* __restrict__ bias,
    float* __restrict__ out)
{
    extern __shared__ char smem[];
    const uint32_t smb = smem_u32(smem);
    const int bid = blockIdx.x;
    const int b   = bid >> 7;
    const int y   = bid & 127;
    const int tid = threadIdx.x;
    const int wid = tid >> 5;
    const int lid = tid & 31;
    const int m0  = wid * 16;            // this warp's px tile

    float d[8][4];                       // accumulators: 8 n-tiles x 4 regs
    #pragma unroll
    for (int i = 0; i < 8; ++i)
        #pragma unroll
        for (int j = 0; j < 4; ++j)
            d[i][j] = 0.0f;

    const float* off_b = offset + (size_t)b * (2 * DGn * KKn * HWp) + (size_t)y * WOn;
    const float* xt_b  = g_xt + (size_t)b * (DGn * Hc * Wc * CGn);

    for (int kk = 0; kk < KKn; ++kk) {
        const int kh = kk / 3;
        const int kw = kk - kh * 3;

        // ---- stage weight tiles (pre-swizzled): 8KB hi + 8KB lo ----
        {
            const uint4* sh = (const uint4*)(g_whi + (size_t)kk * 4096);
            const uint4* sl = (const uint4*)(g_wlo + (size_t)kk * 4096);
            uint4* dh = (uint4*)(smem + SM_W_HI);
            uint4* dl = (uint4*)(smem + SM_W_LO);
            dh[tid] = sh[tid];       dh[tid + 256] = sh[tid + 256];
            dl[tid] = sl[tid];       dl[tid + 256] = sl[tid + 256];
        }

        // ---- sampling: 1024 points (8 dg x 128 px), 4/thread; bf16 hi/lo A tiles ----
        #pragma unroll
        for (int it = 0; it < 4; ++it) {
            const int t  = tid + it * 256;
            const int dg = t >> 7;
            const int px = t & 127;

            const float* op = off_b + (size_t)((dg * KKn + kk) * 2) * HWp + px;
            const float oy = op[0];
            const float ox = op[HWp];

            const float py  = (float)(y - 1 + kh) + oy;
            const float pxx = (float)(px - 1 + kw) + ox;
            const float y0f = floorf(py);
            const float x0f = floorf(pxx);
            const float ly  = py - y0f;
            const float lx  = pxx - x0f;
            const int y0 = (int)y0f;
            const int x0 = (int)x0f;
            const float hy = 1.0f - ly, hx = 1.0f - lx;

            float w00 = hy * hx, w01 = hy * lx, w10 = ly * hx, w11 = ly * lx;
            const bool yv0 = (y0 >= 0) && (y0 < Hc);
            const bool yv1 = (y0 + 1 >= 0) && (y0 + 1 < Hc);
            const bool xv0 = (x0 >= 0) && (x0 < Wc);
            const bool xv1 = (x0 + 1 >= 0) && (x0 + 1 < Wc);
            if (!(yv0 && xv0)) w00 = 0.0f;
            if (!(yv0 && xv1)) w01 = 0.0f;
            if (!(yv1 && xv0)) w10 = 0.0f;
            if (!(yv1 && xv1)) w11 = 0.0f;

            const int iy0 = min(max(y0, 0), Hc - 1);
            const int iy1 = min(max(y0 + 1, 0), Hc - 1);
            const int ix0 = min(max(x0, 0), Wc - 1);
            const int ix1 = min(max(x0 + 1, 0), Wc - 1);

            const float* xg = xt_b + (size_t)dg * (Hc * Wc * CGn);
            const float4* p00 = (const float4*)(xg + (size_t)(iy0 * Wc + ix0) * CGn);
            const float4* p01 = (const float4*)(xg + (size_t)(iy0 * Wc + ix1) * CGn);
            const float4* p10 = (const float4*)(xg + (size_t)(iy1 * Wc + ix0) * CGn);
            const float4* p11 = (const float4*)(xg + (size_t)(iy1 * Wc + ix1) * CGn);

            float v[8];
            #pragma unroll
            for (int g = 0; g < 2; ++g) {
                const float4 a = p00[g], b4 = p01[g], c4 = p10[g], e4 = p11[g];
                v[g * 4 + 0] = w00 * a.x + w01 * b4.x + w10 * c4.x + w11 * e4.x;
                v[g * 4 + 1] = w00 * a.y + w01 * b4.y + w10 * c4.y + w11 * e4.y;
                v[g * 4 + 2] = w00 * a.z + w01 * b4.z + w10 * c4.z + w11 * e4.z;
                v[g * 4 + 3] = w00 * a.w + w01 * b4.w + w10 * c4.w + w11 * e4.w;
            }

            __nv_bfloat162 H2[4], L2[4];
            #pragma unroll
            for (int j = 0; j < 4; ++j) {
                const float a0 = v[2 * j], a1 = v[2 * j + 1];
                const __nv_bfloat16 h0 = __float2bfloat16_rn(a0);
                const __nv_bfloat16 h1 = __float2bfloat16_rn(a1);
                H2[j].x = h0; H2[j].y = h1;
                L2[j].x = __float2bfloat16_rn(a0 - __bfloat162float(h0));
                L2[j].y = __float2bfloat16_rn(a1 - __bfloat162float(h1));
            }
            const uint32_t aoff = SWZ((uint32_t)(px * 128 + dg * 16));
            *(uint4*)(smem + SM_A_HI + aoff) = *(const uint4*)H2;
            *(uint4*)(smem + SM_A_LO + aoff) = *(const uint4*)L2;
        }
        __syncthreads();

        // ---- GEMM phase: HMMA on bf16 hi/lo fragments ----
        uint32_t ah[4][4], al[4][4];
        {
            const uint32_t arow = (uint32_t)(m0 + (lid & 15));
            const uint32_t akg  = (uint32_t)(lid >> 4);      // 0/1 -> k-halves
            #pragma unroll
            for (int ks = 0; ks < 4; ++ks) {
                const uint32_t off = SWZ(arow * 128 + (uint32_t)(ks * 16 + akg * 8) * 2);
                ldsm_x4(ah[ks], smb + SM_A_HI + off);
                ldsm_x4(al[ks], smb + SM_A_LO + off);
            }
        }
        {
            const uint32_t bm  = (uint32_t)(lid >> 3);       // matrix index 0..3
            const uint32_t bj  = (uint32_t)(lid & 7);
            #pragma unroll
            for (int np = 0; np < 4; ++np) {                 // n-pairs (tiles 2np, 2np+1)
                const uint32_t brow = (uint32_t)(np * 16) + (bm >> 1) * 8 + bj;
                #pragma unroll
                for (int ks = 0; ks < 4; ++ks) {
                    const uint32_t off = SWZ(brow * 128 + (uint32_t)(ks * 16) * 2 + (bm & 1) * 16);
                    uint32_t bh[4], bl[4];
                    ldsm_x4(bh, smb + SM_W_HI + off);
                    ldsm_x4(bl, smb + SM_W_LO + off);
                    mma_bf16(d[2 * np],     ah[ks], &bh[0]);
                    mma_bf16(d[2 * np + 1], ah[ks], &bh[2]);
                    mma_bf16(d[2 * np],     ah[ks], &bl[0]);
                    mma_bf16(d[2 * np + 1], ah[ks], &bl[2]);
                    mma_bf16(d[2 * np],     al[ks], &bh[0]);
                    mma_bf16(d[2 * np + 1], al[ks], &bh[2]);
                }
            }
        }
        __syncthreads();
    }

    // ---- epilogue: fragments -> global, +bias ----
    {
        const int px0 = m0 + (lid >> 2);
        float* ob = out + (size_t)b * (COUT * HWp) + (size_t)y * WOn;
        #pragma unroll
        for (int nt = 0; nt < 8; ++nt) {
            const int o0 = nt * 8 + 2 * (lid & 3);
            const float2 bv = *(const float2*)&bias[o0];
            ob[(size_t)o0 * HWp + px0]           = d[nt][0] + bv.x;
            ob[(size_t)(o0 + 1) * HWp + px0]     = d[nt][1] + bv.y;
            ob[(size_t)o0 * HWp + px0 + 8]       = d[nt][2] + bv.x;
            ob[(size_t)(o0 + 1) * HWp + px0 + 8] = d[nt][3] + bv.y;
        }
    }
}

extern "C" void kernel_launch(void* const* d_in, const int* in_sizes, int n_in,
                              void* d_out, int out_size) {
    const float* x      = (const float*)d_in[0];
    const float* offset = (const float*)d_in[1];
    const float* weight = (const float*)d_in[2];
    const float* bias   = (const float*)d_in[3];
    float* out = (float*)d_out;

    cudaFuncSetAttribute(dcn_kernel, cudaFuncAttributeMaxDynamicSharedMemorySize, SM_TOTAL);

    transpose_x_kernel<<<dim3((Hc * Wc) / 256, DGn, Bn), 256>>>(x);
    prep_w_kernel<<<(KKn * COUT * CIN + 255) / 256, 256>>>(weight);
    dcn_kernel<<<Bn * HOn, 256, SM_TOTAL>>>(offset, bias, out);
}

// round 6
// speedup vs baseline: 4.2529x; 1.9864x over previous
#include <cuda_runtime.h>
#include <cuda_fp16.h>
#include <cstdint>

#define Bn   4
#define CIN  64
#define Hc   128
#define Wc   128
#define COUT 64
#define DGn  8
#define KKn  9
#define HOn  128
#define WOn  128
#define CGn  8
#define HWp  (HOn * WOn)

// ---------------- scratch (device globals; no runtime alloc) ----------------
__device__ __half g_xh[Bn * DGn * Hc * Wc * CGn];   // x: [b][dg][y][x][cg] fp16
__device__ __half g_wh[KKn * COUT * CIN];           // weight: per-tap [o][c] fp16, PRE-SWIZZLED SW128

#define SWZ(off) ((off) ^ (((off) >> 3) & 0x70))

// ---------------- smem layout (dynamic, 90112 B) ----------------
#define SM_A     0
#define SM_W     16384
#define SM_TOTAL (16384 + KKn * 8192)

static __device__ __forceinline__ uint32_t smem_u32(const void* p) {
    uint32_t a;
    asm("{ .reg .u64 t; cvta.to.shared.u64 t, %1; cvt.u32.u64 %0, t; }" : "=r"(a) : "l"(p));
    return a;
}
static __device__ __forceinline__ void ldsm_x4(uint32_t* r, uint32_t addr) {
    asm volatile("ldmatrix.sync.aligned.m8n8.x4.shared.b16 {%0,%1,%2,%3}, [%4];"
                 : "=r"(r[0]), "=r"(r[1]), "=r"(r[2]), "=r"(r[3]) : "r"(addr));
}
static __device__ __forceinline__ void mma_f16(float* d, const uint32_t* a, const uint32_t* b) {
    asm volatile("mma.sync.aligned.m16n8k16.row.col.f32.f16.f16.f32 "
                 "{%0,%1,%2,%3}, {%4,%5,%6,%7}, {%8,%9}, {%0,%1,%2,%3};"
                 : "+f"(d[0]), "+f"(d[1]), "+f"(d[2]), "+f"(d[3])
                 : "r"(a[0]), "r"(a[1]), "r"(a[2]), "r"(a[3]), "r"(b[0]), "r"(b[1]));
}

// ---------------------------------------------------------------------------
// x: [B, C=dg*8+cg, H*W] -> g_xh: [b][dg][p][cg]  (fp16, dg-blocked)
// ---------------------------------------------------------------------------
__global__ void transpose_x_kernel(const float* __restrict__ x) {
    __shared__ float s[8][260];
    const int b = blockIdx.z, dg = blockIdx.y, p0 = blockIdx.x * 256, tid = threadIdx.x;
    #pragma unroll
    for (int ch = 0; ch < 8; ++ch)
        s[ch][tid] = x[(size_t)(b * CIN + dg * CGn + ch) * (Hc * Wc) + p0 + tid];
    __syncthreads();
    __half2* dst = (__half2*)(g_xh + ((size_t)(b * DGn + dg) * (Hc * Wc) + p0) * CGn);
    #pragma unroll
    for (int i = 0; i < 4; ++i) {
        const int j = i * 512 + tid * 2;    // even
        dst[i * 256 + tid] = __floats2half2_rn(s[j & 7][j >> 3], s[(j + 1) & 7][(j + 1) >> 3]);
    }
}

// ---------------------------------------------------------------------------
// weight [COUT][CIN][3][3] -> per-tap 64x64 fp16 tile [o][c], SW128-swizzled
// ---------------------------------------------------------------------------
__global__ void prep_w_kernel(const float* __restrict__ w) {
    int idx = blockIdx.x * 256 + threadIdx.x;
    if (idx >= KKn * COUT * CIN) return;
    int kk  = idx / (COUT * CIN);
    int rem = idx - kk * (COUT * CIN);
    int o   = rem / CIN;
    int c   = rem - o * CIN;
    const float v = w[(size_t)(o * CIN + c) * KKn + kk];
    uint32_t off = SWZ((uint32_t)(o * 128 + c * 2));
    g_wh[(size_t)kk * 4096 + off / 2] = __float2half_rn(v);
}

// ---------------------------------------------------------------------------
// Fused deformable conv. Block = one output row (b,y); 8 warps.
// Stage all 9 weight tiles once. Per tap: bilinear-sample 128px x 64c into a
// fp16 A-tile (packed HFMA2 bilinear, SW128), then HMMA: warp w owns px-tile
// [w*16, w*16+16) x all 64 out; fp32 accumulate in registers across 9 taps.
// ---------------------------------------------------------------------------
__global__ void __launch_bounds__(256, 2) dcn_kernel(
    const float* __restrict__ offset,
    const float* __restrict__ bias,
    float* __restrict__ out)
{
    extern __shared__ char smem[];
    const uint32_t smb = smem_u32(smem);
    const int bid = blockIdx.x;
    const int b   = bid >> 7;
    const int y   = bid & 127;
    const int tid = threadIdx.x;
    const int wid = tid >> 5;
    const int lid = tid & 31;
    const int m0  = wid * 16;            // this warp's px tile

    float d[8][4];
    #pragma unroll
    for (int i = 0; i < 8; ++i)
        #pragma unroll
        for (int j = 0; j < 4; ++j)
            d[i][j] = 0.0f;

    // ---- stage ALL weight tiles once: 72KB (pre-swizzled) ----
    {
        const uint4* src = (const uint4*)g_wh;
        uint4* dst = (uint4*)(smem + SM_W);
        #pragma unroll
        for (int i = 0; i < 18; ++i)
            dst[i * 256 + tid] = src[i * 256 + tid];
    }
    // no sync needed yet: first use is after the tap-0 sampling sync

    const float* off_b = offset + (size_t)b * (2 * DGn * KKn * HWp) + (size_t)y * WOn;
    const __half* xh_b = g_xh + (size_t)b * (DGn * Hc * Wc * CGn);

    for (int kk = 0; kk < KKn; ++kk) {
        const int kh = kk / 3;
        const int kw = kk - kh * 3;

        // ---- sampling: 1024 points (8 dg x 128 px), 4/thread ----
        #pragma unroll
        for (int it = 0; it < 4; ++it) {
            const int t  = tid + it * 256;
            const int dg = t >> 7;
            const int px = t & 127;

            const float* op = off_b + (size_t)((dg * KKn + kk) * 2) * HWp + px;
            const float oy = op[0];
            const float ox = op[HWp];

            const float py  = (float)(y - 1 + kh) + oy;
            const float pxx = (float)(px - 1 + kw) + ox;
            const float y0f = floorf(py);
            const float x0f = floorf(pxx);
            const float ly  = py - y0f;
            const float lx  = pxx - x0f;
            const int y0 = (int)y0f;
            const int x0 = (int)x0f;
            const float hy = 1.0f - ly, hx = 1.0f - lx;

            float w00 = hy * hx, w01 = hy * lx, w10 = ly * hx, w11 = ly * lx;
            const bool yv0 = (y0 >= 0) && (y0 < Hc);
            const bool yv1 = (y0 + 1 >= 0) && (y0 + 1 < Hc);
            const bool xv0 = (x0 >= 0) && (x0 < Wc);
            const bool xv1 = (x0 + 1 >= 0) && (x0 + 1 < Wc);
            if (!(yv0 && xv0)) w00 = 0.0f;
            if (!(yv0 && xv1)) w01 = 0.0f;
            if (!(yv1 && xv0)) w10 = 0.0f;
            if (!(yv1 && xv1)) w11 = 0.0f;

            const int iy0 = min(max(y0, 0), Hc - 1);
            const int iy1 = min(max(y0 + 1, 0), Hc - 1);
            const int ix0 = min(max(x0, 0), Wc - 1);
            const int ix1 = min(max(x0 + 1, 0), Wc - 1);

            const __half* xg = xh_b + (size_t)dg * (Hc * Wc * CGn);
            const uint4 q00 = *(const uint4*)(xg + (size_t)(iy0 * Wc + ix0) * CGn);
            const uint4 q01 = *(const uint4*)(xg + (size_t)(iy0 * Wc + ix1) * CGn);
            const uint4 q10 = *(const uint4*)(xg + (size_t)(iy1 * Wc + ix0) * CGn);
            const uint4 q11 = *(const uint4*)(xg + (size_t)(iy1 * Wc + ix1) * CGn);
            const __half2* c00 = (const __half2*)&q00;
            const __half2* c01 = (const __half2*)&q01;
            const __half2* c10 = (const __half2*)&q10;
            const __half2* c11 = (const __half2*)&q11;

            const __half2 wv00 = __float2half2_rn(w00);
            const __half2 wv01 = __float2half2_rn(w01);
            const __half2 wv10 = __float2half2_rn(w10);
            const __half2 wv11 = __float2half2_rn(w11);

            __half2 v2[4];
            #pragma unroll
            for (int j = 0; j < 4; ++j) {
                __half2 acc = __hmul2(c00[j], wv00);
                acc = __hfma2(c01[j], wv01, acc);
                acc = __hfma2(c10[j], wv10, acc);
                acc = __hfma2(c11[j], wv11, acc);
                v2[j] = acc;
            }
            const uint32_t aoff = SWZ((uint32_t)(px * 128 + dg * 16));
            *(uint4*)(smem + SM_A + aoff) = *(const uint4*)v2;
        }
        __syncthreads();

        // ---- GEMM phase: fp16 HMMA, single combo ----
        uint32_t ah[4][4];
        {
            const uint32_t arow = (uint32_t)(m0 + (lid & 15));
            const uint32_t akg  = (uint32_t)(lid >> 4);
            #pragma unroll
            for (int ks = 0; ks < 4; ++ks) {
                const uint32_t off = SWZ(arow * 128 + (uint32_t)(ks * 32) + akg * 16);
                ldsm_x4(ah[ks], smb + SM_A + off);
            }
        }
        {
            const uint32_t wbase = smb + SM_W + (uint32_t)kk * 8192;
            const uint32_t bm  = (uint32_t)(lid >> 3);
            const uint32_t bj  = (uint32_t)(lid & 7);
            #pragma unroll
            for (int np = 0; np < 4; ++np) {
                const uint32_t brow = (uint32_t)(np * 16) + (bm >> 1) * 8 + bj;
                #pragma unroll
                for (int ks = 0; ks < 4; ++ks) {
                    const uint32_t off = SWZ(brow * 128 + (uint32_t)(ks * 32) + (bm & 1) * 16);
                    uint32_t bh[4];
                    ldsm_x4(bh, wbase + off);
                    mma_f16(d[2 * np],     ah[ks], &bh[0]);
                    mma_f16(d[2 * np + 1], ah[ks], &bh[2]);
                }
            }
        }
        __syncthreads();
    }

    // ---- epilogue: fragments -> global, +bias ----
    {
        const int px0 = m0 + (lid >> 2);
        float* ob = out + (size_t)b * (COUT * HWp) + (size_t)y * WOn;
        #pragma unroll
        for (int nt = 0; nt < 8; ++nt) {
            const int o0 = nt * 8 + 2 * (lid & 3);
            const float2 bv = *(const float2*)&bias[o0];
            ob[(size_t)o0 * HWp + px0]           = d[nt][0] + bv.x;
            ob[(size_t)(o0 + 1) * HWp + px0]     = d[nt][1] + bv.y;
            ob[(size_t)o0 * HWp + px0 + 8]       = d[nt][2] + bv.x;
            ob[(size_t)(o0 + 1) * HWp + px0 + 8] = d[nt][3] + bv.y;
        }
    }
}

extern "C" void kernel_launch(void* const* d_in, const int* in_sizes, int n_in,
                              void* d_out, int out_size) {
    const float* x      = (const float*)d_in[0];
    const float* offset = (const float*)d_in[1];
    const float* weight = (const float*)d_in[2];
    const float* bias   = (const float*)d_in[3];
    float* out = (float*)d_out;

    cudaFuncSetAttribute(dcn_kernel, cudaFuncAttributeMaxDynamicSharedMemorySize, SM_TOTAL);

    transpose_x_kernel<<<dim3((Hc * Wc) / 256, DGn, Bn), 256>>>(x);
    prep_w_kernel<<<(KKn * COUT * CIN + 255) / 256, 256>>>(weight);
    dcn_kernel<<<Bn * HOn, 256, SM_TOTAL>>>(offset, bias, out);
}